// round 2
// baseline (speedup 1.0000x reference)
#include <cuda_runtime.h>

#define B_     8
#define HEADS  8
#define D_     128
#define R_     8
#define S_     4096
#define NSLAB  (B_ * HEADS)       // 64

// ---------------- scratch ----------------
__device__ float g_col[NSLAB * D_];        // column sums of x over s
__device__ float g_k[NSLAB * R_];
__device__ float g_c[NSLAB];
__device__ float g_v[NSLAB * D_];          // index == global output row
__device__ float g_wt[NSLAB * D_];         // w~[d] = sum_r k_r * Wq[h,r,d]
__device__ float g_scores[NSLAB * S_];     // raw scores, 1 MB
__device__ float g_pmax[NSLAB * 8];        // per-tile partial maxes
__device__ float g_attn[NSLAB * S_];       // 1 MB

// =======================================================================================
// K1: column sums. 1024 CTAs x 256 threads. CTA = (slab, 8 d-rows); warp owns one row.
// Pure streaming reduction: 1 LDG.128 + 3 FADD per 16B per thread.
// =======================================================================================
__global__ void __launch_bounds__(256) k1_colsum(const float* __restrict__ x)
{
    const int slab = blockIdx.x >> 4;          // /16
    const int dg   = blockIdx.x & 15;
    const int w    = threadIdx.x >> 5;
    const int lane = threadIdx.x & 31;
    const int d    = dg * 8 + w;

    const float4* __restrict__ xr =
        (const float4*)x + ((size_t)slab * D_ + d) * (S_ / 4);

    float acc = 0.f;
    #pragma unroll 8
    for (int i = 0; i < 32; i++) {
        float4 v = xr[i * 32 + lane];
        acc += (v.x + v.y) + (v.z + v.w);
    }
    acc += __shfl_xor_sync(0xffffffffu, acc, 16);
    acc += __shfl_xor_sync(0xffffffffu, acc, 8);
    acc += __shfl_xor_sync(0xffffffffu, acc, 4);
    acc += __shfl_xor_sync(0xffffffffu, acc, 2);
    acc += __shfl_xor_sync(0xffffffffu, acc, 1);
    if (lane == 0) g_col[slab * D_ + d] = acc;
}

// =======================================================================================
// K2: per-slab tiny GEMVs: avg -> k[8], c, v[128], w~[128]. 64 CTAs x 128 threads.
// =======================================================================================
__global__ void __launch_bounds__(128) k2_kv(const float* __restrict__ Wq,
                                             const float* __restrict__ bq,
                                             const float* __restrict__ Wk,
                                             const float* __restrict__ bk,
                                             const float* __restrict__ Wv,
                                             const float* __restrict__ bv)
{
    const int slab = blockIdx.x;
    const int h    = slab & (HEADS - 1);
    const int t    = threadIdx.x;
    const int lane = t & 31;
    const int w    = t >> 5;

    __shared__ __align__(16) float s_avg[D_];
    __shared__ float s_k[R_];

    s_avg[t] = g_col[slab * D_ + t] * (1.0f / (float)S_);
    __syncthreads();

    const float4 av = ((const float4*)s_avg)[lane];

    // v: warp w handles e = w*32 .. w*32+31
    for (int i = 0; i < 32; i++) {
        int e = w * 32 + i;
        float4 wv = ((const float4*)(Wv + ((size_t)h * D_ + e) * D_))[lane];
        float p = av.x * wv.x + av.y * wv.y + av.z * wv.z + av.w * wv.w;
        p += __shfl_xor_sync(0xffffffffu, p, 16);
        p += __shfl_xor_sync(0xffffffffu, p, 8);
        p += __shfl_xor_sync(0xffffffffu, p, 4);
        p += __shfl_xor_sync(0xffffffffu, p, 2);
        p += __shfl_xor_sync(0xffffffffu, p, 1);
        if (lane == 0) g_v[slab * D_ + e] = p + bv[h * D_ + e];
    }

    // k and c: warp 0
    if (w == 0) {
        for (int r = 0; r < R_; r++) {
            float4 wk = ((const float4*)(Wk + ((size_t)h * R_ + r) * D_))[lane];
            float p = av.x * wk.x + av.y * wk.y + av.z * wk.z + av.w * wk.w;
            p += __shfl_xor_sync(0xffffffffu, p, 16);
            p += __shfl_xor_sync(0xffffffffu, p, 8);
            p += __shfl_xor_sync(0xffffffffu, p, 4);
            p += __shfl_xor_sync(0xffffffffu, p, 2);
            p += __shfl_xor_sync(0xffffffffu, p, 1);
            if (lane == 0) s_k[r] = p + bk[h * R_ + r];
        }
        if (lane == 0) {
            float c = 0.f;
            #pragma unroll
            for (int r = 0; r < R_; r++) {
                float kv = s_k[r];
                c += bq[h * R_ + r] * kv;
                g_k[slab * R_ + r] = kv;
            }
            g_c[slab] = c;
        }
    }
    __syncthreads();

    // w~[d] = sum_r k_r * Wq[h,r,d]   (thread t = d)
    {
        float wt = 0.f;
        #pragma unroll
        for (int r = 0; r < R_; r++)
            wt += s_k[r] * Wq[((size_t)h * R_ + r) * D_ + t];
        g_wt[slab * D_ + t] = wt;
    }
}

// =======================================================================================
// K3a: scores[s] = w~ . x[:,s] + c, plus per-tile max. 512 CTAs x 128 threads.
// Reverse launch order: reads x back-to-front so K1's L2-resident tail hits.
// =======================================================================================
__global__ void __launch_bounds__(128) k3a_scores(const float* __restrict__ x)
{
    const int rb   = (int)(gridDim.x - 1 - blockIdx.x);
    const int slab = rb >> 3;
    const int tile = rb & 7;
    const int t    = threadIdx.x;
    const int lane = t & 31;
    const int wid  = t >> 5;

    __shared__ __align__(16) float s_w[D_];
    __shared__ float red[4];

    s_w[t] = g_wt[slab * D_ + t];
    __syncthreads();

    const float4* __restrict__ xb =
        (const float4*)x + (size_t)slab * D_ * (S_ / 4) + tile * 128;

    const float c = g_c[slab];
    float4 acc = make_float4(c, c, c, c);

    #pragma unroll 8
    for (int d = 0; d < D_; d++) {
        float4 xv = __ldcs(&xb[(size_t)d * (S_ / 4) + t]);
        float wv = s_w[d];
        acc.x += wv * xv.x; acc.y += wv * xv.y;
        acc.z += wv * xv.z; acc.w += wv * xv.w;
    }

    ((float4*)(g_scores + (size_t)slab * S_ + tile * 512))[t] = acc;

    float mx = fmaxf(fmaxf(acc.x, acc.y), fmaxf(acc.z, acc.w));
    mx = fmaxf(mx, __shfl_xor_sync(0xffffffffu, mx, 16));
    mx = fmaxf(mx, __shfl_xor_sync(0xffffffffu, mx, 8));
    mx = fmaxf(mx, __shfl_xor_sync(0xffffffffu, mx, 4));
    mx = fmaxf(mx, __shfl_xor_sync(0xffffffffu, mx, 2));
    mx = fmaxf(mx, __shfl_xor_sync(0xffffffffu, mx, 1));
    if (lane == 0) red[wid] = mx;
    __syncthreads();
    if (t == 0) {
        float m = fmaxf(fmaxf(red[0], red[1]), fmaxf(red[2], red[3]));
        g_pmax[slab * 8 + tile] = m;
    }
}

// =======================================================================================
// K3b: global softmax finalize. 64 CTAs x 256 threads. ~2MB traffic.
// =======================================================================================
__global__ void __launch_bounds__(256) k3b_softmax()
{
    const int slab = blockIdx.x;
    const int t    = threadIdx.x;
    const int lane = t & 31;
    const int wid  = t >> 5;

    __shared__ float redsm[8];
    __shared__ float bsm;

    float mx = -3.4e38f;
    #pragma unroll
    for (int i = 0; i < 8; i++) mx = fmaxf(mx, g_pmax[slab * 8 + i]);

    const float4* s4 = (const float4*)(g_scores + (size_t)slab * S_);
    float4 e[4];
    float tot = 0.f;
    #pragma unroll
    for (int i = 0; i < 4; i++) {
        float4 v = s4[i * 256 + t];
        e[i].x = __expf(v.x - mx); e[i].y = __expf(v.y - mx);
        e[i].z = __expf(v.z - mx); e[i].w = __expf(v.w - mx);
        tot += (e[i].x + e[i].y) + (e[i].z + e[i].w);
    }
    #pragma unroll
    for (int o = 16; o; o >>= 1) tot += __shfl_xor_sync(0xffffffffu, tot, o);
    if (lane == 0) redsm[wid] = tot;
    __syncthreads();
    if (wid == 0) {
        float v = (lane < 8) ? redsm[lane] : 0.f;
        #pragma unroll
        for (int o = 4; o; o >>= 1) v += __shfl_xor_sync(0xffffffffu, v, o);
        if (lane == 0) bsm = v;
    }
    __syncthreads();
    const float inv = 1.0f / bsm;

    float4* a4 = (float4*)(g_attn + (size_t)slab * S_);
    #pragma unroll
    for (int i = 0; i < 4; i++)
        a4[i * 256 + t] = make_float4(e[i].x * inv, e[i].y * inv,
                                      e[i].z * inv, e[i].w * inv);
}

// =======================================================================================
// K4: out[row, s] = v[row] * attn[slab, s]. 8192 CTAs x 256 threads. Streaming stores.
// =======================================================================================
__global__ void __launch_bounds__(256) k4_out(float* __restrict__ out)
{
    const int row  = blockIdx.x;
    const int slab = row >> 7;
    const float v  = g_v[row];
    const int t    = threadIdx.x;

    const float4* a4 = (const float4*)(g_attn + (size_t)slab * S_);
    float4* o4 = (float4*)(out + (size_t)row * S_);

    #pragma unroll
    for (int i = 0; i < 4; i++) {
        float4 a = __ldg(&a4[i * 256 + t]);
        __stcs(&o4[i * 256 + t],
               make_float4(v * a.x, v * a.y, v * a.z, v * a.w));
    }
}

// =======================================================================================
extern "C" void kernel_launch(void* const* d_in, const int* in_sizes, int n_in,
                              void* d_out, int out_size)
{
    const float* x  = (const float*)d_in[0];
    const float* Wq = (const float*)d_in[1];
    const float* bq = (const float*)d_in[2];
    const float* Wk = (const float*)d_in[3];
    const float* bk = (const float*)d_in[4];
    const float* Wv = (const float*)d_in[5];
    const float* bv = (const float*)d_in[6];
    float* out = (float*)d_out;

    k1_colsum<<<NSLAB * 16, 256>>>(x);
    k2_kv<<<NSLAB, 128>>>(Wq, bq, Wk, bk, Wv, bv);
    k3a_scores<<<NSLAB * 8, 128>>>(x);
    k3b_softmax<<<NSLAB, 256>>>();
    k4_out<<<B_ * 1024, 256>>>(out);
}

// round 3
// speedup vs baseline: 1.1934x; 1.1934x over previous
#include <cuda_runtime.h>

#define B_     8
#define HEADS  8
#define D_     128
#define R_     8
#define S_     4096
#define NSLAB  (B_ * HEADS)       // 64
#define TILES  8
#define TILE_S (S_ / TILES)       // 512

// ---------------- scratch ----------------
__device__ float g_m[(size_t)NSLAB * S_ * R_];      // [slab][s][r]  8 MB
__device__ float g_colp[NSLAB * TILES * D_];        // per-tile partial column sums
__device__ float g_v[NSLAB * D_];                   // index == global output row
__device__ float g_attn[NSLAB * S_];                // 1 MB

// packed f32x2 helpers (B300: fma.rn.f32x2 / add.rn.f32x2)
__device__ __forceinline__ float2 ffma2(float2 a, float2 b, float2 c) {
    unsigned long long ua = *reinterpret_cast<unsigned long long*>(&a);
    unsigned long long ub = *reinterpret_cast<unsigned long long*>(&b);
    unsigned long long uc = *reinterpret_cast<unsigned long long*>(&c);
    unsigned long long ud;
    asm("fma.rn.f32x2 %0, %1, %2, %3;" : "=l"(ud) : "l"(ua), "l"(ub), "l"(uc));
    return *reinterpret_cast<float2*>(&ud);
}
__device__ __forceinline__ float2 fadd2(float2 a, float2 b) {
    unsigned long long ua = *reinterpret_cast<unsigned long long*>(&a);
    unsigned long long ub = *reinterpret_cast<unsigned long long*>(&b);
    unsigned long long ud;
    asm("add.rn.f32x2 %0, %1, %2;" : "=l"(ud) : "l"(ua), "l"(ub));
    return *reinterpret_cast<float2*>(&ud);
}

// =======================================================================================
// K1: single pass over x. Per (slab, tile of 512 s): m[s][r] = sum_d Wq[h,r,d]*x[d,s]
// (packed FFMA2) + per-tile column-sum partials. 512 CTAs x 128 threads.
// =======================================================================================
__global__ void __launch_bounds__(128) k1_proj(const float* __restrict__ x,
                                               const float* __restrict__ Wq)
{
    const int slab = blockIdx.x >> 3;
    const int tile = blockIdx.x & 7;
    const int h    = slab & (HEADS - 1);
    const int t    = threadIdx.x;
    const int lane = t & 31;
    const int w    = t >> 5;

    __shared__ __align__(16) float2 s_wq[D_ * R_];  // duplicated pairs {w,w}, 8 KB
    __shared__ float s_part[D_ * 33];               // padded: 33 floats per d, ~16.9 KB

    // build duplicated-pair weight table: s_wq[d*8+r] = {Wq[h,r,d], Wq[h,r,d]}
    const float* wqh = Wq + (size_t)h * R_ * D_;
    #pragma unroll
    for (int r = 0; r < R_; r++) {
        float wv = wqh[r * D_ + t];
        s_wq[t * R_ + r] = make_float2(wv, wv);
    }
    __syncthreads();

    const float4* __restrict__ xb =
        (const float4*)x + (size_t)slab * D_ * (S_ / 4) + tile * (TILE_S / 4);

    float2 alo[R_], ahi[R_];
    #pragma unroll
    for (int r = 0; r < R_; r++) { alo[r] = make_float2(0.f, 0.f); ahi[r] = make_float2(0.f, 0.f); }

    #pragma unroll 4
    for (int d = 0; d < D_; d++) {
        float4 xv = xb[d * (S_ / 4) + t];
        float2 xl = make_float2(xv.x, xv.y);
        float2 xh = make_float2(xv.z, xv.w);

        const float4* wrow = (const float4*)(s_wq + d * R_);
        #pragma unroll
        for (int j = 0; j < 4; j++) {
            float4 wp = wrow[j];                       // two duplicated pairs
            float2 w0 = make_float2(wp.x, wp.y);
            float2 w1 = make_float2(wp.z, wp.w);
            alo[2*j]   = ffma2(w0, xl, alo[2*j]);
            ahi[2*j]   = ffma2(w0, xh, ahi[2*j]);
            alo[2*j+1] = ffma2(w1, xl, alo[2*j+1]);
            ahi[2*j+1] = ffma2(w1, xh, ahi[2*j+1]);
        }

        // column-sum partial: cheap 2-level shuffle, 8 partials per warp per d
        float2 rp = fadd2(xl, xh);
        float rs = rp.x + rp.y;
        rs += __shfl_xor_sync(0xffffffffu, rs, 16);
        rs += __shfl_xor_sync(0xffffffffu, rs, 8);
        if (lane < 8) s_part[d * 33 + w * 8 + lane] = rs;
    }
    __syncthreads();

    // finalize this tile's column sums: thread t handles d = t
    {
        float s = 0.f;
        #pragma unroll
        for (int i = 0; i < 32; i++) s += s_part[t * 33 + i];
        g_colp[(slab * TILES + tile) * D_ + t] = s;
    }

    // write m: thread owns s = tile*512 + t*4 .. +3; layout [s][r]
    float4* m4 = (float4*)(g_m + ((size_t)slab * S_ + (size_t)tile * TILE_S + t * 4) * R_);
    m4[0] = make_float4(alo[0].x, alo[1].x, alo[2].x, alo[3].x);
    m4[1] = make_float4(alo[4].x, alo[5].x, alo[6].x, alo[7].x);
    m4[2] = make_float4(alo[0].y, alo[1].y, alo[2].y, alo[3].y);
    m4[3] = make_float4(alo[4].y, alo[5].y, alo[6].y, alo[7].y);
    m4[4] = make_float4(ahi[0].x, ahi[1].x, ahi[2].x, ahi[3].x);
    m4[5] = make_float4(ahi[4].x, ahi[5].x, ahi[6].x, ahi[7].x);
    m4[6] = make_float4(ahi[0].y, ahi[1].y, ahi[2].y, ahi[3].y);
    m4[7] = make_float4(ahi[4].y, ahi[5].y, ahi[6].y, ahi[7].y);
}

// =======================================================================================
// K23: per-slab: avg -> k[8], c, v[128]; then scores = m.k + c, softmax, write attn.
// 64 CTAs x 256 threads.
// =======================================================================================
__global__ void __launch_bounds__(256) k23_kv_softmax(const float* __restrict__ Wk,
                                                      const float* __restrict__ bk,
                                                      const float* __restrict__ Wv,
                                                      const float* __restrict__ bv,
                                                      const float* __restrict__ bq)
{
    const int slab = blockIdx.x;
    const int h    = slab & (HEADS - 1);
    const int t    = threadIdx.x;
    const int lane = t & 31;
    const int w    = t >> 5;

    __shared__ __align__(16) float s_avg[D_];
    __shared__ float s_k[R_];
    __shared__ float s_c;
    __shared__ float red[8];
    __shared__ float red2[8];

    if (t < D_) {
        float a = 0.f;
        #pragma unroll
        for (int i = 0; i < TILES; i++) a += g_colp[(slab * TILES + i) * D_ + t];
        s_avg[t] = a * (1.0f / (float)S_);
    }
    __syncthreads();

    const float4 av = ((const float4*)s_avg)[lane];

    // v: 8 warps, warp w owns e = w*16 .. +15
    #pragma unroll
    for (int i = 0; i < 16; i++) {
        int e = w * 16 + i;
        float4 wv = ((const float4*)(Wv + ((size_t)h * D_ + e) * D_))[lane];
        float p = av.x * wv.x + av.y * wv.y + av.z * wv.z + av.w * wv.w;
        p += __shfl_xor_sync(0xffffffffu, p, 16);
        p += __shfl_xor_sync(0xffffffffu, p, 8);
        p += __shfl_xor_sync(0xffffffffu, p, 4);
        p += __shfl_xor_sync(0xffffffffu, p, 2);
        p += __shfl_xor_sync(0xffffffffu, p, 1);
        if (lane == 0) g_v[slab * D_ + e] = p + bv[h * D_ + e];
    }

    // k and c: warp 0
    if (w == 0) {
        for (int r = 0; r < R_; r++) {
            float4 wk = ((const float4*)(Wk + ((size_t)h * R_ + r) * D_))[lane];
            float p = av.x * wk.x + av.y * wk.y + av.z * wk.z + av.w * wk.w;
            p += __shfl_xor_sync(0xffffffffu, p, 16);
            p += __shfl_xor_sync(0xffffffffu, p, 8);
            p += __shfl_xor_sync(0xffffffffu, p, 4);
            p += __shfl_xor_sync(0xffffffffu, p, 2);
            p += __shfl_xor_sync(0xffffffffu, p, 1);
            if (lane == 0) s_k[r] = p + bk[h * R_ + r];
        }
        if (lane == 0) {
            float c = 0.f;
            #pragma unroll
            for (int r = 0; r < R_; r++) c += bq[h * R_ + r] * s_k[r];
            s_c = c;
        }
    }
    __syncthreads();

    const float k0 = s_k[0], k1 = s_k[1], k2 = s_k[2], k3 = s_k[3];
    const float k4 = s_k[4], k5 = s_k[5], k6 = s_k[6], k7 = s_k[7];
    const float c  = s_c;

    // scores: thread t owns 16 consecutive s = t*16 .. +15
    const float4* m4 = (const float4*)(g_m + (size_t)slab * S_ * R_) + (size_t)t * 32;
    float sc[16];
    float mx = -3.4e38f;
    #pragma unroll
    for (int i = 0; i < 16; i++) {
        float4 a = m4[i * 2];
        float4 b = m4[i * 2 + 1];
        float v = c + k0 * a.x + k1 * a.y + k2 * a.z + k3 * a.w
                    + k4 * b.x + k5 * b.y + k6 * b.z + k7 * b.w;
        sc[i] = v;
        mx = fmaxf(mx, v);
    }
    #pragma unroll
    for (int o = 16; o; o >>= 1) mx = fmaxf(mx, __shfl_xor_sync(0xffffffffu, mx, o));
    if (lane == 0) red[w] = mx;
    __syncthreads();
    mx = red[0];
    #pragma unroll
    for (int i = 1; i < 8; i++) mx = fmaxf(mx, red[i]);

    float tot = 0.f;
    #pragma unroll
    for (int i = 0; i < 16; i++) {
        sc[i] = __expf(sc[i] - mx);
        tot += sc[i];
    }
    #pragma unroll
    for (int o = 16; o; o >>= 1) tot += __shfl_xor_sync(0xffffffffu, tot, o);
    if (lane == 0) red2[w] = tot;
    __syncthreads();
    float bs = red2[0];
    #pragma unroll
    for (int i = 1; i < 8; i++) bs += red2[i];
    const float inv = 1.0f / bs;

    float4* ap = (float4*)(g_attn + (size_t)slab * S_ + (size_t)t * 16);
    #pragma unroll
    for (int i = 0; i < 4; i++)
        ap[i] = make_float4(sc[i*4] * inv, sc[i*4+1] * inv,
                            sc[i*4+2] * inv, sc[i*4+3] * inv);
}

// =======================================================================================
// K4: out[row, s] = v[row] * attn[slab, s]. 8192 CTAs x 256 threads. Streaming stores.
// =======================================================================================
__global__ void __launch_bounds__(256) k4_out(float* __restrict__ out)
{
    const int row  = blockIdx.x;
    const int slab = row >> 7;
    const float v  = g_v[row];
    const int t    = threadIdx.x;

    const float4* a4 = (const float4*)(g_attn + (size_t)slab * S_);
    float4* o4 = (float4*)(out + (size_t)row * S_);

    #pragma unroll
    for (int i = 0; i < 4; i++) {
        float4 a = __ldg(&a4[i * 256 + t]);
        __stcs(&o4[i * 256 + t],
               make_float4(v * a.x, v * a.y, v * a.z, v * a.w));
    }
}

// =======================================================================================
extern "C" void kernel_launch(void* const* d_in, const int* in_sizes, int n_in,
                              void* d_out, int out_size)
{
    const float* x  = (const float*)d_in[0];
    const float* Wq = (const float*)d_in[1];
    const float* bq = (const float*)d_in[2];
    const float* Wk = (const float*)d_in[3];
    const float* bk = (const float*)d_in[4];
    const float* Wv = (const float*)d_in[5];
    const float* bv = (const float*)d_in[6];
    float* out = (float*)d_out;

    k1_proj<<<NSLAB * TILES, 128>>>(x, Wq);
    k23_kv_softmax<<<NSLAB, 256>>>(Wk, bk, Wv, bv, bq);
    k4_out<<<B_ * 1024, 256>>>(out);
}

// round 4
// speedup vs baseline: 1.1981x; 1.0039x over previous
#include <cuda_runtime.h>

#define B_     8
#define HEADS  8
#define D_     128
#define R_     8
#define S_     4096
#define S4     (S_ / 4)
#define NSLAB  (B_ * HEADS)       // 64
#define TILES  8
#define TILE_S (S_ / TILES)       // 512
#define PF     8                  // k1 load-pipeline depth

// ---------------- scratch ----------------
__device__ float g_m[(size_t)NSLAB * S_ * R_];      // [slab][s][r]  8 MB
__device__ float g_colp[NSLAB * TILES * D_];        // per-tile partial column sums
__device__ float g_k[NSLAB * R_];
__device__ float g_c[NSLAB];
__device__ float g_v[NSLAB * D_];                   // index == global output row
__device__ float g_eattn[NSLAB * S_];               // unnormalized exp, 1 MB
__device__ float g_pmax[NSLAB * TILES];
__device__ float g_psum[NSLAB * TILES];

// packed f32x2 helpers
__device__ __forceinline__ float2 ffma2(float2 a, float2 b, float2 c) {
    unsigned long long ua = *reinterpret_cast<unsigned long long*>(&a);
    unsigned long long ub = *reinterpret_cast<unsigned long long*>(&b);
    unsigned long long uc = *reinterpret_cast<unsigned long long*>(&c);
    unsigned long long ud;
    asm("fma.rn.f32x2 %0, %1, %2, %3;" : "=l"(ud) : "l"(ua), "l"(ub), "l"(uc));
    return *reinterpret_cast<float2*>(&ud);
}
__device__ __forceinline__ float2 fadd2(float2 a, float2 b) {
    unsigned long long ua = *reinterpret_cast<unsigned long long*>(&a);
    unsigned long long ub = *reinterpret_cast<unsigned long long*>(&b);
    unsigned long long ud;
    asm("add.rn.f32x2 %0, %1, %2;" : "=l"(ud) : "l"(ua), "l"(ub));
    return *reinterpret_cast<float2*>(&ud);
}

// =======================================================================================
// K1: single pass over x, software-pipelined (depth PF).
// m[s][r] = sum_d Wq[h,r,d]*x[d,s] (FFMA2) + per-tile column-sum partials.
// 512 CTAs x 128 threads.
// =======================================================================================
__global__ void __launch_bounds__(128) k1_proj(const float* __restrict__ x,
                                               const float* __restrict__ Wq)
{
    const int slab = blockIdx.x >> 3;
    const int tile = blockIdx.x & 7;
    const int h    = slab & (HEADS - 1);
    const int t    = threadIdx.x;
    const int lane = t & 31;
    const int w    = t >> 5;

    __shared__ __align__(16) float2 s_wq[D_ * R_];  // duplicated pairs {w,w}, 8 KB
    __shared__ float s_part[D_ * 33];               // padded partials

    const float* wqh = Wq + (size_t)h * R_ * D_;
    #pragma unroll
    for (int r = 0; r < R_; r++) {
        float wv = wqh[r * D_ + t];
        s_wq[t * R_ + r] = make_float2(wv, wv);
    }
    __syncthreads();

    const float4* __restrict__ xb =
        (const float4*)x + (size_t)slab * D_ * S4 + tile * (TILE_S / 4);

    float2 alo[R_], ahi[R_];
    #pragma unroll
    for (int r = 0; r < R_; r++) { alo[r] = make_float2(0.f, 0.f); ahi[r] = make_float2(0.f, 0.f); }

#define K1_PROCESS(xv_, d_)                                                      \
    {                                                                            \
        float2 xl = make_float2((xv_).x, (xv_).y);                               \
        float2 xh = make_float2((xv_).z, (xv_).w);                               \
        const float4* wrow = (const float4*)(s_wq + (d_) * R_);                  \
        _Pragma("unroll")                                                        \
        for (int j = 0; j < 4; j++) {                                            \
            float4 wp = wrow[j];                                                 \
            float2 w0 = make_float2(wp.x, wp.y);                                 \
            float2 w1 = make_float2(wp.z, wp.w);                                 \
            alo[2*j]   = ffma2(w0, xl, alo[2*j]);                                \
            ahi[2*j]   = ffma2(w0, xh, ahi[2*j]);                                \
            alo[2*j+1] = ffma2(w1, xl, alo[2*j+1]);                              \
            ahi[2*j+1] = ffma2(w1, xh, ahi[2*j+1]);                              \
        }                                                                        \
        float2 rp = fadd2(xl, xh);                                               \
        float rs = rp.x + rp.y;                                                  \
        rs += __shfl_xor_sync(0xffffffffu, rs, 16);                              \
        rs += __shfl_xor_sync(0xffffffffu, rs, 8);                               \
        if (lane < 8) s_part[(d_) * 33 + w * 8 + lane] = rs;                     \
    }

    // prologue: fill pipeline
    float4 buf[PF];
    #pragma unroll
    for (int j = 0; j < PF; j++) buf[j] = xb[j * S4 + t];

    // steady state: consume buf[j] for d=db+j, refill with d=db+PF+j
    #pragma unroll 1
    for (int db = 0; db < D_ - PF; db += PF) {
        #pragma unroll
        for (int j = 0; j < PF; j++) {
            float4 xv = buf[j];
            buf[j] = xb[(db + PF + j) * S4 + t];
            K1_PROCESS(xv, db + j);
        }
    }
    // epilogue
    #pragma unroll
    for (int j = 0; j < PF; j++) {
        float4 xv = buf[j];
        K1_PROCESS(xv, (D_ - PF) + j);
    }
#undef K1_PROCESS

    __syncthreads();

    // finalize this tile's column sums: thread t handles d = t
    {
        float s = 0.f;
        #pragma unroll
        for (int i = 0; i < 32; i++) s += s_part[t * 33 + i];
        g_colp[(slab * TILES + tile) * D_ + t] = s;
    }

    // write m: thread owns s = tile*512 + t*4 .. +3; layout [s][r]
    float4* m4 = (float4*)(g_m + ((size_t)slab * S_ + (size_t)tile * TILE_S + t * 4) * R_);
    m4[0] = make_float4(alo[0].x, alo[1].x, alo[2].x, alo[3].x);
    m4[1] = make_float4(alo[4].x, alo[5].x, alo[6].x, alo[7].x);
    m4[2] = make_float4(alo[0].y, alo[1].y, alo[2].y, alo[3].y);
    m4[3] = make_float4(alo[4].y, alo[5].y, alo[6].y, alo[7].y);
    m4[4] = make_float4(ahi[0].x, ahi[1].x, ahi[2].x, ahi[3].x);
    m4[5] = make_float4(ahi[4].x, ahi[5].x, ahi[6].x, ahi[7].x);
    m4[6] = make_float4(ahi[0].y, ahi[1].y, ahi[2].y, ahi[3].y);
    m4[7] = make_float4(ahi[4].y, ahi[5].y, ahi[6].y, ahi[7].y);
}

// =======================================================================================
// K2: per-slab tiny GEMVs: avg -> k[8], c, v[128]. 64 CTAs x 128 threads.
// =======================================================================================
__global__ void __launch_bounds__(128) k2_kv(const float* __restrict__ Wq,
                                             const float* __restrict__ bq,
                                             const float* __restrict__ Wk,
                                             const float* __restrict__ bk,
                                             const float* __restrict__ Wv,
                                             const float* __restrict__ bv)
{
    const int slab = blockIdx.x;
    const int h    = slab & (HEADS - 1);
    const int t    = threadIdx.x;
    const int lane = t & 31;
    const int w    = t >> 5;

    __shared__ __align__(16) float s_avg[D_];
    __shared__ float s_k[R_];

    {
        float a = 0.f;
        #pragma unroll
        for (int i = 0; i < TILES; i++) a += g_colp[(slab * TILES + i) * D_ + t];
        s_avg[t] = a * (1.0f / (float)S_);
    }
    __syncthreads();

    const float4 av = ((const float4*)s_avg)[lane];

    // v: warp w owns e = w*32 .. +31
    for (int i = 0; i < 32; i++) {
        int e = w * 32 + i;
        float4 wv = ((const float4*)(Wv + ((size_t)h * D_ + e) * D_))[lane];
        float p = av.x * wv.x + av.y * wv.y + av.z * wv.z + av.w * wv.w;
        p += __shfl_xor_sync(0xffffffffu, p, 16);
        p += __shfl_xor_sync(0xffffffffu, p, 8);
        p += __shfl_xor_sync(0xffffffffu, p, 4);
        p += __shfl_xor_sync(0xffffffffu, p, 2);
        p += __shfl_xor_sync(0xffffffffu, p, 1);
        if (lane == 0) g_v[slab * D_ + e] = p + bv[h * D_ + e];
    }

    // k and c: warp 0
    if (w == 0) {
        for (int r = 0; r < R_; r++) {
            float4 wk = ((const float4*)(Wk + ((size_t)h * R_ + r) * D_))[lane];
            float p = av.x * wk.x + av.y * wk.y + av.z * wk.z + av.w * wk.w;
            p += __shfl_xor_sync(0xffffffffu, p, 16);
            p += __shfl_xor_sync(0xffffffffu, p, 8);
            p += __shfl_xor_sync(0xffffffffu, p, 4);
            p += __shfl_xor_sync(0xffffffffu, p, 2);
            p += __shfl_xor_sync(0xffffffffu, p, 1);
            if (lane == 0) s_k[r] = p + bk[h * R_ + r];
        }
        if (lane == 0) {
            float c = 0.f;
            #pragma unroll
            for (int r = 0; r < R_; r++) {
                float kv = s_k[r];
                c += bq[h * R_ + r] * kv;
                g_k[slab * R_ + r] = kv;
            }
            g_c[slab] = c;
        }
    }
}

// =======================================================================================
// K3: scores = m.k + c; per-tile max; write UNNORMALIZED exp(sc - tilemax) + tile stats.
// 512 CTAs x 128 threads (thread owns 4 consecutive s).
// =======================================================================================
__global__ void __launch_bounds__(128) k3_scores()
{
    const int slab = blockIdx.x >> 3;
    const int tile = blockIdx.x & 7;
    const int t    = threadIdx.x;
    const int lane = t & 31;
    const int w    = t >> 5;

    __shared__ float redm[4];
    __shared__ float reds[4];
    __shared__ float s_bmx;

    const float* kk = g_k + slab * R_;
    const float k0 = kk[0], k1 = kk[1], k2 = kk[2], k3 = kk[3];
    const float k4 = kk[4], k5 = kk[5], k6 = kk[6], k7 = kk[7];
    const float c  = g_c[slab];

    const size_t sbase = (size_t)slab * S_ + (size_t)tile * TILE_S + t * 4;
    const float4* m4 = (const float4*)(g_m + sbase * R_);

    float sc[4];
    float mx = -3.4e38f;
    #pragma unroll
    for (int i = 0; i < 4; i++) {
        float4 a = m4[i * 2];
        float4 b = m4[i * 2 + 1];
        float v = c + k0 * a.x + k1 * a.y + k2 * a.z + k3 * a.w
                    + k4 * b.x + k5 * b.y + k6 * b.z + k7 * b.w;
        sc[i] = v;
        mx = fmaxf(mx, v);
    }
    #pragma unroll
    for (int o = 16; o; o >>= 1) mx = fmaxf(mx, __shfl_xor_sync(0xffffffffu, mx, o));
    if (lane == 0) redm[w] = mx;
    __syncthreads();
    if (t == 0) s_bmx = fmaxf(fmaxf(redm[0], redm[1]), fmaxf(redm[2], redm[3]));
    __syncthreads();
    const float bmx = s_bmx;

    float4 ev;
    ev.x = __expf(sc[0] - bmx); ev.y = __expf(sc[1] - bmx);
    ev.z = __expf(sc[2] - bmx); ev.w = __expf(sc[3] - bmx);
    float tot = (ev.x + ev.y) + (ev.z + ev.w);
    #pragma unroll
    for (int o = 16; o; o >>= 1) tot += __shfl_xor_sync(0xffffffffu, tot, o);
    if (lane == 0) reds[w] = tot;

    ((float4*)(g_eattn + sbase))[0] = ev;

    __syncthreads();
    if (t == 0) {
        g_pmax[slab * TILES + tile] = bmx;
        g_psum[slab * TILES + tile] = (reds[0] + reds[1]) + (reds[2] + reds[3]);
    }
}

// =======================================================================================
// K4: out[row,s] = v[row] * scale[tile(s)] * eattn[slab,s], where scale folds the
// global softmax normalization. 8192 CTAs x 256 threads. Streaming stores.
// =======================================================================================
__global__ void __launch_bounds__(256) k4_out(float* __restrict__ out)
{
    const int row  = blockIdx.x;
    const int slab = row >> 7;
    const int t    = threadIdx.x;

    __shared__ float s_scale[TILES];

    const float v = g_v[row];

    if (t < TILES) {
        float pm[TILES];
        float gmax = -3.4e38f;
        #pragma unroll
        for (int i = 0; i < TILES; i++) {
            pm[i] = g_pmax[slab * TILES + i];
            gmax = fmaxf(gmax, pm[i]);
        }
        float tot = 0.f;
        #pragma unroll
        for (int i = 0; i < TILES; i++)
            tot += g_psum[slab * TILES + i] * __expf(pm[i] - gmax);
        s_scale[t] = __expf(pm[t] - gmax) / tot;
    }
    __syncthreads();

    const float4* a4 = (const float4*)(g_eattn + (size_t)slab * S_);
    float4* o4 = (float4*)(out + (size_t)row * S_);

    #pragma unroll
    for (int i = 0; i < 4; i++) {
        float sc = v * s_scale[2 * i + (t >> 7)];
        float4 a = __ldg(&a4[i * 256 + t]);
        __stcs(&o4[i * 256 + t],
               make_float4(sc * a.x, sc * a.y, sc * a.z, sc * a.w));
    }
}

// =======================================================================================
extern "C" void kernel_launch(void* const* d_in, const int* in_sizes, int n_in,
                              void* d_out, int out_size)
{
    const float* x  = (const float*)d_in[0];
    const float* Wq = (const float*)d_in[1];
    const float* bq = (const float*)d_in[2];
    const float* Wk = (const float*)d_in[3];
    const float* bk = (const float*)d_in[4];
    const float* Wv = (const float*)d_in[5];
    const float* bv = (const float*)d_in[6];
    float* out = (float*)d_out;

    k1_proj<<<NSLAB * TILES, 128>>>(x, Wq);
    k2_kv<<<NSLAB, 128>>>(Wq, bq, Wk, bk, Wv, bv);
    k3_scores<<<NSLAB * TILES, 128>>>();
    k4_out<<<B_ * 1024, 256>>>(out);
}